// round 1
// baseline (speedup 1.0000x reference)
#include <cuda_runtime.h>

// Problem constants (fixed shapes per reference: B=512, N=65536, db4 L=8)
constexpr int B_SZ   = 512;
constexpr int N_SZ   = 65536;
constexpr int L_FILT = 8;
constexpr int OUTLEN = (N_SZ + L_FILT - 1) / 2;   // 32771
constexpr int PAIRS  = (OUTLEN + 1) / 2;          // 16386 (each thread -> 2 outputs)
constexpr int TPB    = 256;
constexpr int BLK_X  = (PAIRS + TPB - 1) / TPB;   // 65

// cA[b,j] = sum_k ext[2j+k] * rec_lo[k]
// cD[b,j] = sum_k ext[2j+k] * s_k * rec_lo[7-k],  s_k = +1 (k even), -1 (k odd)
// ext index i = 2j+k maps to x index xi = i - 6, reflected:
//   xi < 0   -> -1 - xi
//   xi >= N  -> 2N - 1 - xi
__global__ void __launch_bounds__(TPB)
dwt_db4_kernel(const float* __restrict__ x,
               const float* __restrict__ w,
               float* __restrict__ cA,
               float* __restrict__ cD)
{
    const int b = blockIdx.y;
    const int t = blockIdx.x * blockDim.x + threadIdx.x;   // pair index
    if (t >= PAIRS) return;

    const float* xr = x + (size_t)b * N_SZ;

    // Build filters from weights (uniform loads -> hoisted / L1-broadcast)
    float hA[8], hD[8];
#pragma unroll
    for (int k = 0; k < 8; ++k) hA[k] = __ldg(w + k);
#pragma unroll
    for (int k = 0; k < 8; ++k) hD[k] = (k & 1) ? -hA[7 - k] : hA[7 - k];

    // Gather 12 inputs covering x[4t-8 .. 4t+3]
    float v[12];
    const int base = 4 * t - 8;
    if (t >= 2 && t < PAIRS - 2) {
        // Fast interior path: 3 aligned float4 loads (rows are 256KB-aligned)
        const float4 va = *reinterpret_cast<const float4*>(xr + base);
        const float4 vb = *reinterpret_cast<const float4*>(xr + base + 4);
        const float4 vc = *reinterpret_cast<const float4*>(xr + base + 8);
        v[0] = va.x; v[1] = va.y; v[2]  = va.z; v[3]  = va.w;
        v[4] = vb.x; v[5] = vb.y; v[6]  = vb.z; v[7]  = vb.w;
        v[8] = vc.x; v[9] = vc.y; v[10] = vc.z; v[11] = vc.w;
    } else {
        // Boundary path with symmetric reflection
#pragma unroll
        for (int m = 0; m < 12; ++m) {
            int xi = base + m;
            if (xi < 0)          xi = -1 - xi;
            else if (xi >= N_SZ) xi = 2 * N_SZ - 1 - xi;
            v[m] = xr[xi];
        }
    }

    // j0 = 2t uses v[k+2] (x index 4t-6+k); j1 = 2t+1 uses v[k+4]
    float a0 = 0.f, d0 = 0.f, a1 = 0.f, d1 = 0.f;
#pragma unroll
    for (int k = 0; k < 8; ++k) {
        a0 = fmaf(v[k + 2], hA[k], a0);
        d0 = fmaf(v[k + 2], hD[k], d0);
        a1 = fmaf(v[k + 4], hA[k], a1);
        d1 = fmaf(v[k + 4], hD[k], d1);
    }

    const size_t orow = (size_t)b * OUTLEN;
    const int j0 = 2 * t;
    cA[orow + j0] = a0;
    cD[orow + j0] = d0;
    if (j0 + 1 < OUTLEN) {
        cA[orow + j0 + 1] = a1;
        cD[orow + j0 + 1] = d1;
    }
}

__global__ void copy_x3_kernel(const float* __restrict__ src, float* __restrict__ dst, int n)
{
    const int i = blockIdx.x * blockDim.x + threadIdx.x;
    if (i < n) dst[i] = src[i];
}

extern "C" void kernel_launch(void* const* d_in, const int* in_sizes, int n_in,
                              void* d_out, int out_size)
{
    const float* x1 = (const float*)d_in[0];   // (512, 65536)
    // d_in[1] = x2 (unused by reference output)
    const float* x3 = (const float*)d_in[2];   // (512, 1, 8)
    const float* w  = (const float*)d_in[3];   // (8,)

    float* out = (float*)d_out;
    float* cA  = out;                                   // (B, OUTLEN)
    float* cD  = out + (size_t)B_SZ * OUTLEN;           // (B, 1, OUTLEN)
    float* ox3 = out + 2 * (size_t)B_SZ * OUTLEN;       // (B, 1, 8)

    dim3 grid(BLK_X, B_SZ);
    dwt_db4_kernel<<<grid, TPB>>>(x1, w, cA, cD);

    const int n3 = B_SZ * 8;
    copy_x3_kernel<<<(n3 + 255) / 256, 256>>>(x3, ox3, n3);
}